// round 11
// baseline (speedup 1.0000x reference)
#include <cuda_runtime.h>

// Problem constants (fixed shapes from reference)
#define BB 4
#define NN 19
#define HH 512
#define WW 512
#define HWc (HH * WW)          // 262144
#define CC 57
#define PAIRS (BB * NN)        // 76
#define THREADS 256

#define NSTREAM (148 * 7)                    // 1036 stream CTAs (flat bce sum)
#define NDISK PAIRS                          // 76 disk CTAs
#define NWORK (NSTREAM + NDISK)              // 1112 workers (+1 watcher) = 1113 <= 8*148
#define NV4 (BB * NN * (HWc / 4))            // 4,980,736 float4 of logits

#define RAD 40
#define BBOX 81                              // 2*RAD+1
#define BBOX2 (BBOX * BBOX)                  // 6561

// Accumulators. Zero at module load; watcher resets after consuming ->
// state identical on every graph replay.
__device__ double g_shot;                    // global sum of bce hot terms (double: atomic-order-safe)
__device__ float g_bce[PAIRS];               // per-pair: -sum_heat(l)
__device__ float g_l1x[PAIRS];
__device__ float g_l1y[PAIRS];
__device__ float g_cnt[PAIRS];
__device__ unsigned int g_count = 0;

__global__ __launch_bounds__(THREADS, 8) void hm_main_kernel(
    const float* __restrict__ fm, const float* __restrict__ lms,
    float* __restrict__ out)
{
    const int warp = threadIdx.x >> 5;
    const int lane = threadIdx.x & 31;

    // ---------------- watcher CTA: finalize ----------------
    if (blockIdx.x == NWORK) {
        const int tid = threadIdx.x;
        if (tid == 0) {
            volatile unsigned int* vc = &g_count;
            while (*vc != (unsigned int)NWORK) __nanosleep(200);
        }
        __syncthreads();
        __threadfence();   // acquire: accumulator REDs visible after count

        float t = 0.0f;
        if (tid < PAIRS) {
            const float vb = __ldcg(&g_bce[tid]);     // = -sum_heat(l)
            const float vx = __ldcg(&g_l1x[tid]);
            const float vy = __ldcg(&g_l1y[tid]);
            const float vn = __ldcg(&g_cnt[tid]);
            t = 2.0f * vb * (1.0f / (float)HWc) + (vx + vy) / vn;
        }
        #pragma unroll
        for (int o = 16; o > 0; o >>= 1)
            t += __shfl_down_sync(0xFFFFFFFFu, t, o);

        __shared__ float s[8];
        if (lane == 0) s[warp] = t;
        __syncthreads();
        if (tid == 0) {
            float sum = 0.0f;
            #pragma unroll
            for (int i = 0; i < 8; i++) sum += s[i];
            // add the global hot-term once: 2*S_hot/HW (spread over all pairs)
            sum += (float)(2.0 * g_shot * (1.0 / (double)HWc));
            out[0] = sum / (float)PAIRS;
        }
        // reset state for the next graph replay (end state == initial state)
        if (tid < PAIRS) {
            g_bce[tid] = 0.0f; g_l1x[tid] = 0.0f;
            g_l1y[tid] = 0.0f; g_cnt[tid] = 0.0f;
        }
        if (tid == 0) { g_shot = 0.0; g_count = 0; }
        return;
    }

    // ---------------- disk CTAs: per-pair heat-region terms ----------------
    if (blockIdx.x >= NSTREAM) {
        const int pair = blockIdx.x - NSTREAM;   // 0..75
        const int b = pair / NN;
        const int n = pair % NN;
        const float lx = lms[pair * 2 + 0];
        const float ly = lms[pair * 2 + 1];
        const int x = (int)(lx * (float)HH);
        const int y = (int)(ly * (float)WW);

        const size_t base = ((size_t)(b * CC + n)) * (size_t)HWc;
        const float* __restrict__ pL = fm + base;
        const float* __restrict__ pX = fm + base + (size_t)NN * HWc;
        const float* __restrict__ pY = fm + base + (size_t)(2 * NN) * HWc;

        float subL = 0.0f, l1x = 0.0f, l1y = 0.0f;
        int cnt = 0;

        for (int idx = threadIdx.x; idx < BBOX2; idx += THREADS) {
            const int r  = idx / BBOX;       // 0..80
            const int cc = idx - r * BBOX;   // 0..80
            const int di = r - RAD;
            const int dj = cc - RAD;
            const int gi = x + di;
            const int gj = y + dj;
            if ((unsigned)gi < HH && (unsigned)gj < WW &&
                di * di + dj * dj <= RAD * RAD) {
                const int off = gi * WW + gj;
                const float l  = __ldg(pL + off);
                const float px = __ldg(pX + off);
                const float py = __ldg(pY + off);
                subL += l;
                l1x += fabsf(px + (float)di * (1.0f / 40.0f));  // |px - (-di/40)|
                l1y += fabsf(py + (float)dj * (1.0f / 40.0f));
                cnt++;
            }
        }

        float c = (float)cnt;
        float nb = -subL;   // contribution to bce: -sum_heat(l)
        #pragma unroll
        for (int o = 16; o > 0; o >>= 1) {
            nb  += __shfl_down_sync(0xFFFFFFFFu, nb, o);
            l1x += __shfl_down_sync(0xFFFFFFFFu, l1x, o);
            l1y += __shfl_down_sync(0xFFFFFFFFu, l1y, o);
            c   += __shfl_down_sync(0xFFFFFFFFu, c, o);
        }
        __shared__ float d0[8], d1[8], d2[8], d3[8];
        if (lane == 0) { d0[warp] = nb; d1[warp] = l1x; d2[warp] = l1y; d3[warp] = c; }
        __syncthreads();
        if (threadIdx.x == 0) {
            float v0 = 0.f, v1 = 0.f, v2 = 0.f, v3 = 0.f;
            #pragma unroll
            for (int i = 0; i < 8; i++) {
                v0 += d0[i]; v1 += d1[i]; v2 += d2[i]; v3 += d3[i];
            }
            atomicAdd(&g_bce[pair], v0);
            atomicAdd(&g_l1x[pair], v1);
            atomicAdd(&g_l1y[pair], v2);
            atomicAdd(&g_cnt[pair], v3);
            __threadfence();
            atomicAdd(&g_count, 1u);
        }
        return;
    }

    // ---------------- stream CTAs: flat bce hot-term sum ----------------
    // S_hot = sum over ALL logits pixels of max(l,0) + log(1+exp(-|l|)).
    // Default caching (__ldg): 86MB working set fits 126MB L2 -> graph replays
    // after the first hit L2 instead of HBM.
    const float4* __restrict__ pL = (const float4*)fm;

    float bce_lin = 0.0f;   // Sum of (l + |l|)  == 2*max(l,0)
    float bce_log = 0.0f;   // Sum of log(1+exp(-|l|)) via log-of-products

    const int T = NSTREAM * THREADS;         // total stream threads
    int i = blockIdx.x * THREADS + threadIdx.x;

    // main loop: 4 independent LDG.128 in flight (16 buffer regs, no spill)
    for (; i + 3 * T < NV4; i += 4 * T) {
        const float4 A = __ldg(pL + i);
        const float4 B = __ldg(pL + i + T);
        const float4 C = __ldg(pL + i + 2 * T);
        const float4 D = __ldg(pL + i + 3 * T);

        #pragma unroll
        for (int q = 0; q < 4; q++) {
            const float4 L = (q == 0) ? A : (q == 1) ? B : (q == 2) ? C : D;
            const float a0 = fabsf(L.x), a1 = fabsf(L.y);
            const float a2 = fabsf(L.z), a3 = fabsf(L.w);
            bce_lin += ((L.x + a0) + (L.y + a1)) + ((L.z + a2) + (L.w + a3));
            const float e0 = 1.0f + __expf(-a0);
            const float e1 = 1.0f + __expf(-a1);
            const float e2 = 1.0f + __expf(-a2);
            const float e3 = 1.0f + __expf(-a3);
            bce_log += __logf((e0 * e1) * (e2 * e3));
        }
    }
    // remainder
    for (; i < NV4; i += T) {
        const float4 L = __ldg(pL + i);
        const float a0 = fabsf(L.x), a1 = fabsf(L.y);
        const float a2 = fabsf(L.z), a3 = fabsf(L.w);
        bce_lin += ((L.x + a0) + (L.y + a1)) + ((L.z + a2) + (L.w + a3));
        const float e0 = 1.0f + __expf(-a0);
        const float e1 = 1.0f + __expf(-a1);
        const float e2 = 1.0f + __expf(-a2);
        const float e3 = 1.0f + __expf(-a3);
        bce_log += __logf((e0 * e1) * (e2 * e3));
    }

    float bce = fmaf(0.5f, bce_lin, bce_log);

    #pragma unroll
    for (int o = 16; o > 0; o >>= 1)
        bce += __shfl_down_sync(0xFFFFFFFFu, bce, o);

    __shared__ float s0[8];
    if (lane == 0) s0[warp] = bce;
    __syncthreads();
    // warps 1..7 retire here; only thread0 pays the fence.

    if (threadIdx.x == 0) {
        float v0 = 0.f;
        #pragma unroll
        for (int i2 = 0; i2 < 8; i2++) v0 += s0[i2];
        atomicAdd(&g_shot, (double)v0);  // double accumulation: order-stable
        __threadfence();                 // order data RED before the count RED
        atomicAdd(&g_count, 1u);
    }
}

extern "C" void kernel_launch(void* const* d_in, const int* in_sizes, int n_in,
                              void* d_out, int out_size)
{
    const float* fm  = (const float*)d_in[0];   // feature_maps (4,57,512,512) f32
    const float* lms = (const float*)d_in[1];   // landmarks (4,19,2) f32
    float* out = (float*)d_out;

    hm_main_kernel<<<NWORK + 1, THREADS>>>(fm, lms, out);
}

// round 12
// speedup vs baseline: 1.2538x; 1.2538x over previous
#include <cuda_runtime.h>

// Problem constants (fixed shapes from reference)
#define BB 4
#define NN 19
#define HH 512
#define WW 512
#define HWc (HH * WW)          // 262144
#define CC 57
#define PAIRS (BB * NN)        // 76
#define THREADS 256

#define NDISK PAIRS                          // disk CTAs: blockIdx 0..75
#define NSTREAM 608                          // stream CTAs: 76..683
#define NWORK (NDISK + NSTREAM)              // 684 workers; watcher = 684
#define NV4 (BB * NN * (HWc / 4))            // 4,980,736 = 19 * 2^18 float4
#define TSTR (NSTREAM * THREADS)             // 155,648 = 19*2^13; NV4/TSTR = 32 exactly

#define RAD 40
#define BBOX 81                              // 2*RAD+1
#define BBOX2 (BBOX * BBOX)                  // 6561

// Accumulators. Zero at module load; watcher resets after consuming ->
// state identical on every graph replay.
__device__ double g_shot;                    // global sum of bce hot terms
__device__ float g_bce[PAIRS];               // per-pair: -sum_heat(l)
__device__ float g_l1x[PAIRS];
__device__ float g_l1y[PAIRS];
__device__ float g_cnt[PAIRS];
__device__ unsigned int g_count = 0;

__global__ __launch_bounds__(THREADS, 5) void hm_main_kernel(
    const float* __restrict__ fm, const float* __restrict__ lms,
    float* __restrict__ out)
{
    const int warp = threadIdx.x >> 5;
    const int lane = threadIdx.x & 31;

    // ---------------- watcher CTA: finalize ----------------
    if (blockIdx.x == NWORK) {
        const int tid = threadIdx.x;
        if (tid == 0) {
            volatile unsigned int* vc = &g_count;
            while (*vc != (unsigned int)NWORK) __nanosleep(200);
        }
        __syncthreads();
        __threadfence();   // acquire: accumulator REDs visible after count

        float t = 0.0f;
        if (tid < PAIRS) {
            const float vb = __ldcg(&g_bce[tid]);     // = -sum_heat(l)
            const float vx = __ldcg(&g_l1x[tid]);
            const float vy = __ldcg(&g_l1y[tid]);
            const float vn = __ldcg(&g_cnt[tid]);
            t = 2.0f * vb * (1.0f / (float)HWc) + (vx + vy) / vn;
        }
        #pragma unroll
        for (int o = 16; o > 0; o >>= 1)
            t += __shfl_down_sync(0xFFFFFFFFu, t, o);

        __shared__ float s[8];
        if (lane == 0) s[warp] = t;
        __syncthreads();
        if (tid == 0) {
            float sum = 0.0f;
            #pragma unroll
            for (int i = 0; i < 8; i++) sum += s[i];
            // add the global hot-term once: 2*S_hot/HW (spread over all pairs)
            sum += (float)(2.0 * g_shot * (1.0 / (double)HWc));
            out[0] = sum / (float)PAIRS;
        }
        // reset state for the next graph replay (end state == initial state)
        if (tid < PAIRS) {
            g_bce[tid] = 0.0f; g_l1x[tid] = 0.0f;
            g_l1y[tid] = 0.0f; g_cnt[tid] = 0.0f;
        }
        if (tid == 0) { g_shot = 0.0; g_count = 0; }
        return;
    }

    // ---------------- disk CTAs (0..75): per-pair heat-region terms ----------------
    if (blockIdx.x < NDISK) {
        const int pair = blockIdx.x;             // 0..75
        const int b = pair / NN;
        const int n = pair % NN;
        const float lx = lms[pair * 2 + 0];
        const float ly = lms[pair * 2 + 1];
        const int x = (int)(lx * (float)HH);
        const int y = (int)(ly * (float)WW);

        const size_t base = ((size_t)(b * CC + n)) * (size_t)HWc;
        const float* __restrict__ pL = fm + base;
        const float* __restrict__ pX = fm + base + (size_t)NN * HWc;
        const float* __restrict__ pY = fm + base + (size_t)(2 * NN) * HWc;

        float subL = 0.0f, l1x = 0.0f, l1y = 0.0f;
        int cnt = 0;

        for (int idx = threadIdx.x; idx < BBOX2; idx += THREADS) {
            const int r  = idx / BBOX;       // 0..80
            const int cc = idx - r * BBOX;   // 0..80
            const int di = r - RAD;
            const int dj = cc - RAD;
            const int gi = x + di;
            const int gj = y + dj;
            if ((unsigned)gi < HH && (unsigned)gj < WW &&
                di * di + dj * dj <= RAD * RAD) {
                const int off = gi * WW + gj;
                const float l  = __ldg(pL + off);
                const float px = __ldg(pX + off);
                const float py = __ldg(pY + off);
                subL += l;
                l1x += fabsf(px + (float)di * (1.0f / 40.0f));  // |px - (-di/40)|
                l1y += fabsf(py + (float)dj * (1.0f / 40.0f));
                cnt++;
            }
        }

        float c = (float)cnt;
        float nb = -subL;   // contribution to bce: -sum_heat(l)
        #pragma unroll
        for (int o = 16; o > 0; o >>= 1) {
            nb  += __shfl_down_sync(0xFFFFFFFFu, nb, o);
            l1x += __shfl_down_sync(0xFFFFFFFFu, l1x, o);
            l1y += __shfl_down_sync(0xFFFFFFFFu, l1y, o);
            c   += __shfl_down_sync(0xFFFFFFFFu, c, o);
        }
        __shared__ float d0[8], d1[8], d2[8], d3[8];
        if (lane == 0) { d0[warp] = nb; d1[warp] = l1x; d2[warp] = l1y; d3[warp] = c; }
        __syncthreads();
        if (threadIdx.x == 0) {
            float v0 = 0.f, v1 = 0.f, v2 = 0.f, v3 = 0.f;
            #pragma unroll
            for (int i = 0; i < 8; i++) {
                v0 += d0[i]; v1 += d1[i]; v2 += d2[i]; v3 += d3[i];
            }
            atomicAdd(&g_bce[pair], v0);
            atomicAdd(&g_l1x[pair], v1);
            atomicAdd(&g_l1y[pair], v2);
            atomicAdd(&g_cnt[pair], v3);
            __threadfence();
            atomicAdd(&g_count, 1u);
        }
        return;
    }

    // ---------------- stream CTAs (76..683): flat bce hot-term sum ----------------
    // Each thread: exactly 32 float4 (8 quads), software-pipelined prefetch.
    const float4* __restrict__ pL = (const float4*)fm;

    float bce_lin = 0.0f;   // Sum of (l + |l|)  == 2*max(l,0)
    float bce_log = 0.0f;   // Sum of log(1+exp(-|l|)) via log-of-products

    const int i0 = (blockIdx.x - NDISK) * THREADS + threadIdx.x;

    float4 c0, c1, c2, c3, n0, n1, n2, n3;
    c0 = __ldcs(pL + i0);
    c1 = __ldcs(pL + i0 + TSTR);
    c2 = __ldcs(pL + i0 + 2 * TSTR);
    c3 = __ldcs(pL + i0 + 3 * TSTR);

    #pragma unroll
    for (int it = 0; it < 8; it++) {
        const int nb = i0 + (4 * it + 4) * TSTR;
        if (it < 7) {
            n0 = __ldcs(pL + nb);
            n1 = __ldcs(pL + nb + TSTR);
            n2 = __ldcs(pL + nb + 2 * TSTR);
            n3 = __ldcs(pL + nb + 3 * TSTR);
        }
        #pragma unroll
        for (int q = 0; q < 4; q++) {
            const float4 L = (q == 0) ? c0 : (q == 1) ? c1 : (q == 2) ? c2 : c3;
            const float a0 = fabsf(L.x), a1 = fabsf(L.y);
            const float a2 = fabsf(L.z), a3 = fabsf(L.w);
            bce_lin += ((L.x + a0) + (L.y + a1)) + ((L.z + a2) + (L.w + a3));
            const float e0 = 1.0f + __expf(-a0);
            const float e1 = 1.0f + __expf(-a1);
            const float e2 = 1.0f + __expf(-a2);
            const float e3 = 1.0f + __expf(-a3);
            bce_log += __logf((e0 * e1) * (e2 * e3));
        }
        c0 = n0; c1 = n1; c2 = n2; c3 = n3;   // full unroll -> register renaming
    }

    float bce = fmaf(0.5f, bce_lin, bce_log);

    #pragma unroll
    for (int o = 16; o > 0; o >>= 1)
        bce += __shfl_down_sync(0xFFFFFFFFu, bce, o);

    __shared__ float s0[8];
    if (lane == 0) s0[warp] = bce;
    __syncthreads();
    // warps 1..7 retire here; only thread0 pays the fence.

    if (threadIdx.x == 0) {
        float v0 = 0.f;
        #pragma unroll
        for (int i2 = 0; i2 < 8; i2++) v0 += s0[i2];
        atomicAdd(&g_shot, (double)v0);  // fire-and-forget, single scalar
        __threadfence();                 // order data RED before the count RED
        atomicAdd(&g_count, 1u);
    }
}

extern "C" void kernel_launch(void* const* d_in, const int* in_sizes, int n_in,
                              void* d_out, int out_size)
{
    const float* fm  = (const float*)d_in[0];   // feature_maps (4,57,512,512) f32
    const float* lms = (const float*)d_in[1];   // landmarks (4,19,2) f32
    float* out = (float*)d_out;

    hm_main_kernel<<<NWORK + 1, THREADS>>>(fm, lms, out);
}

// round 13
// speedup vs baseline: 1.2879x; 1.0272x over previous
#include <cuda_runtime.h>

// Problem constants (fixed shapes from reference)
#define BB 4
#define NN 19
#define HH 512
#define WW 512
#define HWc (HH * WW)          // 262144
#define CC 57
#define PAIRS (BB * NN)        // 76
#define THREADS 256

#define NDISK PAIRS                          // disk CTAs: blockIdx 0..75
#define NSTREAM 512                          // stream CTAs: 76..587
#define NWORK (NDISK + NSTREAM)              // 588 workers; watcher = 588
#define NV4 (BB * NN * (HWc / 4))            // 4,980,736 float4 of logits
#define TSTR (NSTREAM * THREADS)             // 131,072; NV4/TSTR = 38 exactly
#define PER_THREAD 38                        // float4 per stream thread
#define DEPTH 8                              // rolling prefetch distance

#define RAD 40
#define BBOX 81                              // 2*RAD+1
#define BBOX2 (BBOX * BBOX)                  // 6561

// Accumulators. Zero at module load; watcher resets after consuming ->
// state identical on every graph replay.
__device__ double g_shot;                    // global sum of bce hot terms
__device__ float g_bce[PAIRS];               // per-pair: -sum_heat(l)
__device__ float g_l1x[PAIRS];
__device__ float g_l1y[PAIRS];
__device__ float g_cnt[PAIRS];
__device__ unsigned int g_count = 0;

__global__ __launch_bounds__(THREADS, 4) void hm_main_kernel(
    const float* __restrict__ fm, const float* __restrict__ lms,
    float* __restrict__ out)
{
    const int warp = threadIdx.x >> 5;
    const int lane = threadIdx.x & 31;

    // ---------------- watcher CTA: finalize ----------------
    if (blockIdx.x == NWORK) {
        const int tid = threadIdx.x;
        if (tid == 0) {
            volatile unsigned int* vc = &g_count;
            while (*vc != (unsigned int)NWORK) __nanosleep(200);
        }
        __syncthreads();
        __threadfence();   // acquire: accumulator REDs visible after count

        float t = 0.0f;
        if (tid < PAIRS) {
            const float vb = __ldcg(&g_bce[tid]);     // = -sum_heat(l)
            const float vx = __ldcg(&g_l1x[tid]);
            const float vy = __ldcg(&g_l1y[tid]);
            const float vn = __ldcg(&g_cnt[tid]);
            t = 2.0f * vb * (1.0f / (float)HWc) + (vx + vy) / vn;
        }
        #pragma unroll
        for (int o = 16; o > 0; o >>= 1)
            t += __shfl_down_sync(0xFFFFFFFFu, t, o);

        __shared__ float s[8];
        if (lane == 0) s[warp] = t;
        __syncthreads();
        if (tid == 0) {
            float sum = 0.0f;
            #pragma unroll
            for (int i = 0; i < 8; i++) sum += s[i];
            // add the global hot-term once: 2*S_hot/HW (spread over all pairs)
            sum += (float)(2.0 * g_shot * (1.0 / (double)HWc));
            out[0] = sum / (float)PAIRS;
        }
        // reset state for the next graph replay (end state == initial state)
        if (tid < PAIRS) {
            g_bce[tid] = 0.0f; g_l1x[tid] = 0.0f;
            g_l1y[tid] = 0.0f; g_cnt[tid] = 0.0f;
        }
        if (tid == 0) { g_shot = 0.0; g_count = 0; }
        return;
    }

    // ---------------- disk CTAs (0..75): per-pair heat-region terms ----------------
    if (blockIdx.x < NDISK) {
        const int pair = blockIdx.x;             // 0..75
        const int b = pair / NN;
        const int n = pair % NN;
        const float lx = lms[pair * 2 + 0];
        const float ly = lms[pair * 2 + 1];
        const int x = (int)(lx * (float)HH);
        const int y = (int)(ly * (float)WW);

        const size_t base = ((size_t)(b * CC + n)) * (size_t)HWc;
        const float* __restrict__ pL = fm + base;
        const float* __restrict__ pX = fm + base + (size_t)NN * HWc;
        const float* __restrict__ pY = fm + base + (size_t)(2 * NN) * HWc;

        float subL = 0.0f, l1x = 0.0f, l1y = 0.0f;
        int cnt = 0;

        for (int idx = threadIdx.x; idx < BBOX2; idx += THREADS) {
            const int r  = idx / BBOX;       // 0..80
            const int cc = idx - r * BBOX;   // 0..80
            const int di = r - RAD;
            const int dj = cc - RAD;
            const int gi = x + di;
            const int gj = y + dj;
            if ((unsigned)gi < HH && (unsigned)gj < WW &&
                di * di + dj * dj <= RAD * RAD) {
                const int off = gi * WW + gj;
                const float l  = __ldg(pL + off);
                const float px = __ldg(pX + off);
                const float py = __ldg(pY + off);
                subL += l;
                l1x += fabsf(px + (float)di * (1.0f / 40.0f));  // |px - (-di/40)|
                l1y += fabsf(py + (float)dj * (1.0f / 40.0f));
                cnt++;
            }
        }

        float c = (float)cnt;
        float nb = -subL;   // contribution to bce: -sum_heat(l)
        #pragma unroll
        for (int o = 16; o > 0; o >>= 1) {
            nb  += __shfl_down_sync(0xFFFFFFFFu, nb, o);
            l1x += __shfl_down_sync(0xFFFFFFFFu, l1x, o);
            l1y += __shfl_down_sync(0xFFFFFFFFu, l1y, o);
            c   += __shfl_down_sync(0xFFFFFFFFu, c, o);
        }
        __shared__ float d0[8], d1[8], d2[8], d3[8];
        if (lane == 0) { d0[warp] = nb; d1[warp] = l1x; d2[warp] = l1y; d3[warp] = c; }
        __syncthreads();
        if (threadIdx.x == 0) {
            float v0 = 0.f, v1 = 0.f, v2 = 0.f, v3 = 0.f;
            #pragma unroll
            for (int i = 0; i < 8; i++) {
                v0 += d0[i]; v1 += d1[i]; v2 += d2[i]; v3 += d3[i];
            }
            atomicAdd(&g_bce[pair], v0);
            atomicAdd(&g_l1x[pair], v1);
            atomicAdd(&g_l1y[pair], v2);
            atomicAdd(&g_cnt[pair], v3);
            __threadfence();
            atomicAdd(&g_count, 1u);
        }
        return;
    }

    // ---------------- stream CTAs (76..587): flat bce hot-term sum ----------------
    // Each thread: exactly 38 float4. Rolling ring of 8 buffers: consume slot,
    // immediately re-issue its replacement load (distance 8) -> ~8 LDG.128
    // constantly in flight per warp.
    const float4* __restrict__ pL = (const float4*)fm;

    float bce_lin = 0.0f;   // Sum of (l + |l|)  == 2*max(l,0)
    float bce_log = 0.0f;   // Sum of log(1+exp(-|l|)) via log-of-products

    const int i0 = (blockIdx.x - NDISK) * THREADS + threadIdx.x;

    float4 buf[DEPTH];
    #pragma unroll
    for (int j = 0; j < DEPTH; j++)
        buf[j] = __ldcs(pL + i0 + j * TSTR);

    #pragma unroll
    for (int k = 0; k < PER_THREAD; k++) {
        const float4 L = buf[k % DEPTH];
        if (k + DEPTH < PER_THREAD)
            buf[k % DEPTH] = __ldcs(pL + i0 + (k + DEPTH) * TSTR);

        const float a0 = fabsf(L.x), a1 = fabsf(L.y);
        const float a2 = fabsf(L.z), a3 = fabsf(L.w);
        bce_lin += ((L.x + a0) + (L.y + a1)) + ((L.z + a2) + (L.w + a3));
        const float e0 = 1.0f + __expf(-a0);
        const float e1 = 1.0f + __expf(-a1);
        const float e2 = 1.0f + __expf(-a2);
        const float e3 = 1.0f + __expf(-a3);
        bce_log += __logf((e0 * e1) * (e2 * e3));
    }

    float bce = fmaf(0.5f, bce_lin, bce_log);

    #pragma unroll
    for (int o = 16; o > 0; o >>= 1)
        bce += __shfl_down_sync(0xFFFFFFFFu, bce, o);

    __shared__ float s0[8];
    if (lane == 0) s0[warp] = bce;
    __syncthreads();
    // warps 1..7 retire here; only thread0 pays the fence.

    if (threadIdx.x == 0) {
        float v0 = 0.f;
        #pragma unroll
        for (int i2 = 0; i2 < 8; i2++) v0 += s0[i2];
        atomicAdd(&g_shot, (double)v0);  // fire-and-forget, single scalar
        __threadfence();                 // order data RED before the count RED
        atomicAdd(&g_count, 1u);
    }
}

extern "C" void kernel_launch(void* const* d_in, const int* in_sizes, int n_in,
                              void* d_out, int out_size)
{
    const float* fm  = (const float*)d_in[0];   // feature_maps (4,57,512,512) f32
    const float* lms = (const float*)d_in[1];   // landmarks (4,19,2) f32
    float* out = (float*)d_out;

    hm_main_kernel<<<NWORK + 1, THREADS>>>(fm, lms, out);
}